// round 1
// baseline (speedup 1.0000x reference)
#include <cuda_runtime.h>

#define BATCH  2
#define SEQ    2048
#define DMODEL 1024
#define NHEAD  16
#define HDIM   64
#define MROWS  (BATCH * SEQ)       // 4096

// Scratch (allocation-free rule: __device__ globals)
__device__ float g_q[BATCH * NHEAD * SEQ * HDIM];   // [b,h,s,hd]
__device__ float g_k[BATCH * NHEAD * SEQ * HDIM];
__device__ float g_v[BATCH * NHEAD * SEQ * HDIM];
__device__ float g_ctx[MROWS * DMODEL];             // [b*s, d]

// ---------------------------------------------------------------------------
// SGEMM: C[M,N] = A[M,K] @ W[N,K]^T + bias   (torch Linear convention)
// BM=BN=128, BK=8, 256 threads, 8x8 per-thread tile.
// MODE 0: out[m*DMODEL + n]
// MODE 1: out[((b*NHEAD+h)*SEQ + s)*HDIM + hd]   (fused head transpose)
// Sizes hardcoded-compatible: M%128==0, N%128==0, K%8==0.
// ---------------------------------------------------------------------------
template <int MODE>
__global__ __launch_bounds__(256)
void sgemm_kernel(const float* __restrict__ A,
                  const float* __restrict__ W,
                  const float* __restrict__ bias,
                  float* __restrict__ out)
{
    const int K = DMODEL;
    __shared__ float As[8][128];
    __shared__ float Ws[8][128];

    const int tid = threadIdx.x;
    const int tr  = tid >> 4;        // 0..15
    const int tc  = tid & 15;        // 0..15
    const int mBase = blockIdx.y * 128;
    const int nBase = blockIdx.x * 128;

    // Load mapping: each thread loads one float4 per tile from A and W.
    const int loadRow = tid >> 1;        // 0..127
    const int loadCol = (tid & 1) * 4;   // 0 or 4

    const float* Aptr = A + (mBase + loadRow) * K + loadCol;
    const float* Wptr = W + (nBase + loadRow) * K + loadCol;

    float acc[8][8];
    #pragma unroll
    for (int i = 0; i < 8; i++)
        #pragma unroll
        for (int j = 0; j < 8; j++) acc[i][j] = 0.0f;

    for (int kt = 0; kt < K; kt += 8) {
        float4 a = *reinterpret_cast<const float4*>(Aptr + kt);
        float4 w = *reinterpret_cast<const float4*>(Wptr + kt);
        As[loadCol + 0][loadRow] = a.x;
        As[loadCol + 1][loadRow] = a.y;
        As[loadCol + 2][loadRow] = a.z;
        As[loadCol + 3][loadRow] = a.w;
        Ws[loadCol + 0][loadRow] = w.x;
        Ws[loadCol + 1][loadRow] = w.y;
        Ws[loadCol + 2][loadRow] = w.z;
        Ws[loadCol + 3][loadRow] = w.w;
        __syncthreads();

        #pragma unroll
        for (int k = 0; k < 8; k++) {
            float ra[8], rb[8];
            #pragma unroll
            for (int i = 0; i < 8; i++) ra[i] = As[k][tr * 8 + i];
            #pragma unroll
            for (int j = 0; j < 8; j++) rb[j] = Ws[k][tc * 8 + j];
            #pragma unroll
            for (int i = 0; i < 8; i++)
                #pragma unroll
                for (int j = 0; j < 8; j++)
                    acc[i][j] = fmaf(ra[i], rb[j], acc[i][j]);
        }
        __syncthreads();
    }

    #pragma unroll
    for (int i = 0; i < 8; i++) {
        const int m = mBase + tr * 8 + i;
        #pragma unroll
        for (int j = 0; j < 8; j++) {
            const int n = nBase + tc * 8 + j;
            const float val = acc[i][j] + bias[n];
            if (MODE == 0) {
                out[m * DMODEL + n] = val;
            } else {
                const int b  = m >> 11;          // / SEQ (2048)
                const int s  = m & 2047;
                const int h  = n >> 6;           // / HDIM
                const int hd = n & 63;
                out[(((b * NHEAD + h) * SEQ) + s) * HDIM + hd] = val;
            }
        }
    }
}

// ---------------------------------------------------------------------------
// Flash attention (causal), fp32.
// grid = (SEQ/64, BATCH*NHEAD), 256 threads. 64x64 tiles, 4x4 per thread.
// Dynamic smem: 4 arrays of 64x65 floats (Q, K, V, P) = 66560 B.
// ---------------------------------------------------------------------------
#define TPAD 65

__global__ __launch_bounds__(256)
void attn_kernel(float* __restrict__ ctx)
{
    extern __shared__ float sm[];
    float* Qs = sm;                    // [64][65]
    float* Ks = Qs + 64 * TPAD;
    float* Vs = Ks + 64 * TPAD;
    float* Ps = Vs + 64 * TPAD;

    const int tid = threadIdx.x;
    const int tr  = tid >> 4;          // 0..15 -> rows tr*4..tr*4+3
    const int tc  = tid & 15;          // 0..15 -> cols tc*4..tc*4+3
    const int qt  = blockIdx.x;
    const int bh  = blockIdx.y;
    const int qBase = qt * 64;

    const float* Q  = g_q + (size_t)bh * SEQ * HDIM;
    const float* Kp = g_k + (size_t)bh * SEQ * HDIM;
    const float* Vp = g_v + (size_t)bh * SEQ * HDIM;

    // Load Q tile (64x64): 1024 float4s, 4 per thread.
    #pragma unroll
    for (int t = 0; t < 4; t++) {
        const int f4  = tid + t * 256;
        const int row = f4 >> 4;
        const int col = (f4 & 15) * 4;
        float4 v4 = *reinterpret_cast<const float4*>(Q + (qBase + row) * HDIM + col);
        Qs[row * TPAD + col + 0] = v4.x;
        Qs[row * TPAD + col + 1] = v4.y;
        Qs[row * TPAD + col + 2] = v4.z;
        Qs[row * TPAD + col + 3] = v4.w;
    }

    float m_i[4], l_i[4], O[4][4];
    #pragma unroll
    for (int i = 0; i < 4; i++) {
        m_i[i] = -1e30f;
        l_i[i] = 0.0f;
        #pragma unroll
        for (int j = 0; j < 4; j++) O[i][j] = 0.0f;
    }

    for (int kt = 0; kt <= qt; kt++) {
        const int kBase = kt * 64;
        __syncthreads();   // protect Ks/Vs/Ps from previous iteration's readers

        // Load K and V tiles
        #pragma unroll
        for (int t = 0; t < 4; t++) {
            const int f4  = tid + t * 256;
            const int row = f4 >> 4;
            const int col = (f4 & 15) * 4;
            float4 kv = *reinterpret_cast<const float4*>(Kp + (kBase + row) * HDIM + col);
            float4 vv = *reinterpret_cast<const float4*>(Vp + (kBase + row) * HDIM + col);
            Ks[row * TPAD + col + 0] = kv.x;
            Ks[row * TPAD + col + 1] = kv.y;
            Ks[row * TPAD + col + 2] = kv.z;
            Ks[row * TPAD + col + 3] = kv.w;
            Vs[row * TPAD + col + 0] = vv.x;
            Vs[row * TPAD + col + 1] = vv.y;
            Vs[row * TPAD + col + 2] = vv.z;
            Vs[row * TPAD + col + 3] = vv.w;
        }
        __syncthreads();

        // Scores: s[i][j] = Q[tr*4+i] . K[tc*4+j]
        float s[4][4];
        #pragma unroll
        for (int i = 0; i < 4; i++)
            #pragma unroll
            for (int j = 0; j < 4; j++) s[i][j] = 0.0f;

        #pragma unroll 16
        for (int kk = 0; kk < 64; kk++) {
            float rq[4], rk[4];
            #pragma unroll
            for (int i = 0; i < 4; i++) rq[i] = Qs[(tr * 4 + i) * TPAD + kk];
            #pragma unroll
            for (int j = 0; j < 4; j++) rk[j] = Ks[(tc * 4 + j) * TPAD + kk];
            #pragma unroll
            for (int i = 0; i < 4; i++)
                #pragma unroll
                for (int j = 0; j < 4; j++)
                    s[i][j] = fmaf(rq[i], rk[j], s[i][j]);
        }

        const float scale = 0.125f;    // HD^-0.5 = 1/8
        const bool diag = (kt == qt);
        #pragma unroll
        for (int i = 0; i < 4; i++)
            #pragma unroll
            for (int j = 0; j < 4; j++) {
                s[i][j] *= scale;
                if (diag && (tc * 4 + j > tr * 4 + i)) s[i][j] = -1e30f;
            }

        // Row-wise online softmax. Row r owned by 16 threads (same tr).
        float mt[4];
        #pragma unroll
        for (int i = 0; i < 4; i++) {
            mt[i] = fmaxf(fmaxf(s[i][0], s[i][1]), fmaxf(s[i][2], s[i][3]));
            #pragma unroll
            for (int off = 8; off >= 1; off >>= 1)
                mt[i] = fmaxf(mt[i], __shfl_xor_sync(0xffffffffu, mt[i], off, 16));
        }

        float corr[4], ls[4];
        #pragma unroll
        for (int i = 0; i < 4; i++) {
            const float m_new = fmaxf(m_i[i], mt[i]);
            corr[i] = __expf(m_i[i] - m_new);
            m_i[i]  = m_new;
            ls[i]   = 0.0f;
            #pragma unroll
            for (int j = 0; j < 4; j++) {
                const float p = __expf(s[i][j] - m_new);
                s[i][j] = p;
                ls[i]  += p;
            }
            #pragma unroll
            for (int off = 8; off >= 1; off >>= 1)
                ls[i] += __shfl_xor_sync(0xffffffffu, ls[i], off, 16);
            l_i[i] = l_i[i] * corr[i] + ls[i];
            #pragma unroll
            for (int j = 0; j < 4; j++) O[i][j] *= corr[i];
        }

        // P tile to smem
        #pragma unroll
        for (int i = 0; i < 4; i++)
            #pragma unroll
            for (int j = 0; j < 4; j++)
                Ps[(tr * 4 + i) * TPAD + tc * 4 + j] = s[i][j];
        __syncthreads();

        // O += P @ V
        #pragma unroll 16
        for (int kk = 0; kk < 64; kk++) {
            float rp[4], rv[4];
            #pragma unroll
            for (int i = 0; i < 4; i++) rp[i] = Ps[(tr * 4 + i) * TPAD + kk];
            #pragma unroll
            for (int j = 0; j < 4; j++) rv[j] = Vs[kk * TPAD + tc * 4 + j];
            #pragma unroll
            for (int i = 0; i < 4; i++)
                #pragma unroll
                for (int j = 0; j < 4; j++)
                    O[i][j] = fmaf(rp[i], rv[j], O[i][j]);
        }
    }

    // Epilogue: ctx[(b*SEQ + s)*DMODEL + h*HDIM + hd]
    const int b = bh / NHEAD;
    const int h = bh % NHEAD;
    #pragma unroll
    for (int i = 0; i < 4; i++) {
        const float inv = 1.0f / l_i[i];
        const int srow = qBase + tr * 4 + i;
        #pragma unroll
        for (int j = 0; j < 4; j++)
            ctx[(b * SEQ + srow) * DMODEL + h * HDIM + tc * 4 + j] = O[i][j] * inv;
    }
}

// ---------------------------------------------------------------------------
// Launch
// ---------------------------------------------------------------------------
extern "C" void kernel_launch(void* const* d_in, const int* in_sizes, int n_in,
                              void* d_out, int out_size)
{
    const float* x  = (const float*)d_in[0];
    const float* wq = (const float*)d_in[1];
    const float* bq = (const float*)d_in[2];
    const float* wk = (const float*)d_in[3];
    const float* bk = (const float*)d_in[4];
    const float* wv = (const float*)d_in[5];
    const float* bv = (const float*)d_in[6];
    const float* wo = (const float*)d_in[7];
    const float* bo = (const float*)d_in[8];
    float* out = (float*)d_out;

    float *qp, *kp, *vp, *cp;
    cudaGetSymbolAddress((void**)&qp, g_q);
    cudaGetSymbolAddress((void**)&kp, g_k);
    cudaGetSymbolAddress((void**)&vp, g_v);
    cudaGetSymbolAddress((void**)&cp, g_ctx);

    dim3 gemmGrid(DMODEL / 128, MROWS / 128);   // (8, 32)
    dim3 blk(256);

    // Q/K/V projections (fused head-transpose epilogue)
    sgemm_kernel<1><<<gemmGrid, blk>>>(x, wq, bq, qp);
    sgemm_kernel<1><<<gemmGrid, blk>>>(x, wk, bk, kp);
    sgemm_kernel<1><<<gemmGrid, blk>>>(x, wv, bv, vp);

    // Attention
    const int smemBytes = 4 * 64 * TPAD * sizeof(float);   // 66560
    cudaFuncSetAttribute(attn_kernel, cudaFuncAttributeMaxDynamicSharedMemorySize, smemBytes);
    dim3 attnGrid(SEQ / 64, BATCH * NHEAD);     // (32, 32)
    attn_kernel<<<attnGrid, blk, smemBytes>>>(cp);

    // Output projection
    sgemm_kernel<0><<<gemmGrid, blk>>>(cp, wo, bo, out);
}

// round 3
// speedup vs baseline: 1.5666x; 1.5666x over previous
#include <cuda_runtime.h>
#include <cuda_bf16.h>
#include <cstdint>

#define BATCH  2
#define SEQ    2048
#define DMODEL 1024
#define NHEAD  16
#define HDIM   64
#define MROWS  (BATCH * SEQ)       // 4096

// ---------------------------------------------------------------------------
// Scratch (allocation-free rule: __device__ globals)
// ---------------------------------------------------------------------------
__device__ float g_q[BATCH * NHEAD * SEQ * HDIM];   // [b,h,s,hd] fp32
__device__ float g_k[BATCH * NHEAD * SEQ * HDIM];
__device__ float g_v[BATCH * NHEAD * SEQ * HDIM];
__device__ float g_ctx[MROWS * DMODEL];             // [b*s, d] fp32

__device__ __nv_bfloat16 g_xh[MROWS * DMODEL];      // x split hi/lo
__device__ __nv_bfloat16 g_xl[MROWS * DMODEL];
__device__ __nv_bfloat16 g_ch[MROWS * DMODEL];      // ctx split hi/lo
__device__ __nv_bfloat16 g_cl[MROWS * DMODEL];
__device__ __nv_bfloat16 g_wh[4][DMODEL * DMODEL];  // wq,wk,wv,wo hi
__device__ __nv_bfloat16 g_wl[4][DMODEL * DMODEL];  // wq,wk,wv,wo lo

// ---------------------------------------------------------------------------
// Warp-MMA helpers (mma.sync / ldmatrix — base compute_103 PTX, no 'a' features)
// ---------------------------------------------------------------------------
__device__ __forceinline__ uint32_t smem_u32(const void* p) {
    uint32_t a;
    asm("{ .reg .u64 t; cvta.to.shared.u64 t, %1; cvt.u32.u64 %0, t; }"
        : "=r"(a) : "l"(p));
    return a;
}

__device__ __forceinline__ void ldmatrix_x4(uint32_t* r, uint32_t addr) {
    asm volatile("ldmatrix.sync.aligned.m8n8.x4.shared.b16 {%0,%1,%2,%3}, [%4];"
                 : "=r"(r[0]), "=r"(r[1]), "=r"(r[2]), "=r"(r[3]) : "r"(addr));
}

__device__ __forceinline__ void ldmatrix_x2(uint32_t* r, uint32_t addr) {
    asm volatile("ldmatrix.sync.aligned.m8n8.x2.shared.b16 {%0,%1}, [%2];"
                 : "=r"(r[0]), "=r"(r[1]) : "r"(addr));
}

__device__ __forceinline__ void mma_bf16(float* c, const uint32_t* a, const uint32_t* b) {
    asm volatile(
        "mma.sync.aligned.m16n8k16.row.col.f32.bf16.bf16.f32 "
        "{%0,%1,%2,%3}, {%4,%5,%6,%7}, {%8,%9}, {%0,%1,%2,%3};"
        : "+f"(c[0]), "+f"(c[1]), "+f"(c[2]), "+f"(c[3])
        : "r"(a[0]), "r"(a[1]), "r"(a[2]), "r"(a[3]), "r"(b[0]), "r"(b[1]));
}

// ---------------------------------------------------------------------------
// fp32 -> (bf16 hi, bf16 lo) split
// ---------------------------------------------------------------------------
__global__ __launch_bounds__(256)
void split_bf16_kernel(const float* __restrict__ in,
                       __nv_bfloat16* __restrict__ hi,
                       __nv_bfloat16* __restrict__ lo, int n)
{
    int i4 = (blockIdx.x * blockDim.x + threadIdx.x) * 4;
    if (i4 >= n) return;
    float4 f = *reinterpret_cast<const float4*>(in + i4);
    float fs[4] = {f.x, f.y, f.z, f.w};
    __nv_bfloat162 hv[2], lv[2];
    #pragma unroll
    for (int j = 0; j < 2; j++) {
        __nv_bfloat16 h0 = __float2bfloat16(fs[2 * j]);
        __nv_bfloat16 h1 = __float2bfloat16(fs[2 * j + 1]);
        __nv_bfloat16 l0 = __float2bfloat16(fs[2 * j] - __bfloat162float(h0));
        __nv_bfloat16 l1 = __float2bfloat16(fs[2 * j + 1] - __bfloat162float(h1));
        hv[j].x = h0; hv[j].y = h1;
        lv[j].x = l0; lv[j].y = l1;
    }
    *reinterpret_cast<__nv_bfloat162*>(hi + i4)     = hv[0];
    *reinterpret_cast<__nv_bfloat162*>(hi + i4 + 2) = hv[1];
    *reinterpret_cast<__nv_bfloat162*>(lo + i4)     = lv[0];
    *reinterpret_cast<__nv_bfloat162*>(lo + i4 + 2) = lv[1];
}

// ---------------------------------------------------------------------------
// Warp-MMA GEMM: C[M,N] = A[M,K] @ W[N,K]^T + bias  (split-bf16, fp32 accum)
// CTA 128x128 tile, 8 warps (2x4), warp tile 64x32, K-chunk 64.
// SMEM: 4 tiles (Ah, Al, Bh, Bl), each 128 x 72 bf16 (pad 8) = 73728 B total.
// MODE 0: out[m*DMODEL + n]
// MODE 1: out[((b*NHEAD+h)*SEQ + s)*HDIM + hd]   (fused head transpose)
// ---------------------------------------------------------------------------
#define LDT       72
#define TILE_ELEM (128 * LDT)            // 9216 bf16
#define TILE_B    (TILE_ELEM * 2)        // 18432 bytes
#define GEMM_SMEM (4 * TILE_B)           // 73728 bytes

template <int MODE>
__global__ __launch_bounds__(256)
void mma_gemm(const __nv_bfloat16* __restrict__ Ah,
              const __nv_bfloat16* __restrict__ Al,
              const __nv_bfloat16* __restrict__ Bh,
              const __nv_bfloat16* __restrict__ Bl,
              const float* __restrict__ bias,
              float* __restrict__ out)
{
    extern __shared__ __align__(16) char smem[];
    __nv_bfloat16* sT = reinterpret_cast<__nv_bfloat16*>(smem);
    const uint32_t sbase = smem_u32(smem);

    const int tid  = threadIdx.x;
    const int wid  = tid >> 5;
    const int lane = tid & 31;
    const int mBase = blockIdx.y * 128;
    const int nBase = blockIdx.x * 128;
    const int warp_m = (wid >> 2) * 64;     // 0 or 64
    const int warp_n = (wid & 3) * 32;      // 0,32,64,96

    float acc[4][4][4];
    #pragma unroll
    for (int mi = 0; mi < 4; mi++)
        #pragma unroll
        for (int ni = 0; ni < 4; ni++)
            #pragma unroll
            for (int e = 0; e < 4; e++) acc[mi][ni][e] = 0.0f;

    // Precompute ldmatrix base addresses (byte offsets into smem)
    // A frag row address: (warp_m + mi*16 + (lane&15))*LDT + k0 + (lane>>4)*8
    // B frag row address: (warp_n + ni*8  + (lane&7)) *LDT + k0 + ((lane>>3)&1)*8
    const uint32_t aRow = (uint32_t)(warp_m + (lane & 15)) * LDT + (lane >> 4) * 8;
    const uint32_t bRow = (uint32_t)(warp_n + (lane & 7)) * LDT + ((lane >> 3) & 1) * 8;
    const uint32_t uA = sbase + 2 * aRow;                 // Ah tile at offset 0
    const uint32_t uB = sbase + 2 * TILE_B / 2 * 2 + 2 * bRow;  // Bh tile at offset 2*TILE_B
    // (Ah at 0, Al at TILE_B, Bh at 2*TILE_B, Bl at 3*TILE_B)

    for (int kc = 0; kc < DMODEL; kc += 64) {
        __syncthreads();   // protect smem from previous iteration's readers

        // Load 4 tiles: each 128 rows x 64 bf16 (8 uint4 per row -> 1024 uint4)
        #pragma unroll
        for (int t = 0; t < 4; t++) {
            const __nv_bfloat16* src = (t == 0) ? Ah : (t == 1) ? Al : (t == 2) ? Bh : Bl;
            const int rb = (t < 2) ? mBase : nBase;
            __nv_bfloat16* dst = sT + t * TILE_ELEM;
            #pragma unroll
            for (int it = 0; it < 4; it++) {
                const int slot = tid + it * 256;   // 0..1023
                const int row  = slot >> 3;
                const int c8   = slot & 7;
                uint4 v = *reinterpret_cast<const uint4*>(
                    src + (size_t)(rb + row) * DMODEL + kc + c8 * 8);
                *reinterpret_cast<uint4*>(dst + row * LDT + c8 * 8) = v;
            }
        }
        __syncthreads();

        #pragma unroll
        for (int ks = 0; ks < 4; ks++) {
            const uint32_t kOff = 2 * (uint32_t)(ks * 16);
            uint32_t ah[4][4], al[4][4], bh[4][2], bl[4][2];
            #pragma unroll
            for (int mi = 0; mi < 4; mi++) {
                const uint32_t addr = uA + kOff + 2 * (uint32_t)(mi * 16) * LDT;
                ldmatrix_x4(ah[mi], addr);
                ldmatrix_x4(al[mi], addr + TILE_B);
            }
            #pragma unroll
            for (int ni = 0; ni < 4; ni++) {
                const uint32_t addr = uB + kOff + 2 * (uint32_t)(ni * 8) * LDT;
                ldmatrix_x2(bh[ni], addr);
                ldmatrix_x2(bl[ni], addr + TILE_B);
            }
            #pragma unroll
            for (int mi = 0; mi < 4; mi++)
                #pragma unroll
                for (int ni = 0; ni < 4; ni++) {
                    mma_bf16(acc[mi][ni], ah[mi], bh[ni]);
                    mma_bf16(acc[mi][ni], al[mi], bh[ni]);
                    mma_bf16(acc[mi][ni], ah[mi], bl[ni]);
                }
        }
    }

    // Epilogue: acc frag (mi,ni): c0,c1 at (row = warp_m+mi*16+lane/4,
    //   col = warp_n+ni*8+(lane%4)*2), c2,c3 at row+8.
    const int rBase = mBase + warp_m + (lane >> 2);
    const int cBase = nBase + warp_n + (lane & 3) * 2;
    #pragma unroll
    for (int mi = 0; mi < 4; mi++) {
        #pragma unroll
        for (int ni = 0; ni < 4; ni++) {
            #pragma unroll
            for (int half = 0; half < 2; half++) {
                const int m = rBase + mi * 16 + half * 8;
                #pragma unroll
                for (int e = 0; e < 2; e++) {
                    const int n = cBase + ni * 8 + e;
                    const float val = acc[mi][ni][half * 2 + e] + bias[n];
                    if (MODE == 0) {
                        out[(size_t)m * DMODEL + n] = val;
                    } else {
                        const int b  = m >> 11;      // / SEQ
                        const int s  = m & 2047;
                        const int h  = n >> 6;       // / HDIM
                        const int hd = n & 63;
                        out[(((size_t)(b * NHEAD + h) * SEQ) + s) * HDIM + hd] = val;
                    }
                }
            }
        }
    }
}

// ---------------------------------------------------------------------------
// Flash attention (causal), fp32 — unchanged from R1.
// grid = (SEQ/64, BATCH*NHEAD), 256 threads. 64x64 tiles, 4x4 per thread.
// ---------------------------------------------------------------------------
#define TPAD 65

__global__ __launch_bounds__(256)
void attn_kernel(float* __restrict__ ctx)
{
    extern __shared__ float sm[];
    float* Qs = sm;                    // [64][65]
    float* Ks = Qs + 64 * TPAD;
    float* Vs = Ks + 64 * TPAD;
    float* Ps = Vs + 64 * TPAD;

    const int tid = threadIdx.x;
    const int tr  = tid >> 4;
    const int tc  = tid & 15;
    const int qt  = blockIdx.x;
    const int bh  = blockIdx.y;
    const int qBase = qt * 64;

    const float* Q  = g_q + (size_t)bh * SEQ * HDIM;
    const float* Kp = g_k + (size_t)bh * SEQ * HDIM;
    const float* Vp = g_v + (size_t)bh * SEQ * HDIM;

    #pragma unroll
    for (int t = 0; t < 4; t++) {
        const int f4  = tid + t * 256;
        const int row = f4 >> 4;
        const int col = (f4 & 15) * 4;
        float4 v4 = *reinterpret_cast<const float4*>(Q + (qBase + row) * HDIM + col);
        Qs[row * TPAD + col + 0] = v4.x;
        Qs[row * TPAD + col + 1] = v4.y;
        Qs[row * TPAD + col + 2] = v4.z;
        Qs[row * TPAD + col + 3] = v4.w;
    }

    float m_i[4], l_i[4], O[4][4];
    #pragma unroll
    for (int i = 0; i < 4; i++) {
        m_i[i] = -1e30f;
        l_i[i] = 0.0f;
        #pragma unroll
        for (int j = 0; j < 4; j++) O[i][j] = 0.0f;
    }

    for (int kt = 0; kt <= qt; kt++) {
        const int kBase = kt * 64;
        __syncthreads();

        #pragma unroll
        for (int t = 0; t < 4; t++) {
            const int f4  = tid + t * 256;
            const int row = f4 >> 4;
            const int col = (f4 & 15) * 4;
            float4 kv = *reinterpret_cast<const float4*>(Kp + (kBase + row) * HDIM + col);
            float4 vv = *reinterpret_cast<const float4*>(Vp + (kBase + row) * HDIM + col);
            Ks[row * TPAD + col + 0] = kv.x;
            Ks[row * TPAD + col + 1] = kv.y;
            Ks[row * TPAD + col + 2] = kv.z;
            Ks[row * TPAD + col + 3] = kv.w;
            Vs[row * TPAD + col + 0] = vv.x;
            Vs[row * TPAD + col + 1] = vv.y;
            Vs[row * TPAD + col + 2] = vv.z;
            Vs[row * TPAD + col + 3] = vv.w;
        }
        __syncthreads();

        float s[4][4];
        #pragma unroll
        for (int i = 0; i < 4; i++)
            #pragma unroll
            for (int j = 0; j < 4; j++) s[i][j] = 0.0f;

        #pragma unroll 16
        for (int kk = 0; kk < 64; kk++) {
            float rq[4], rk[4];
            #pragma unroll
            for (int i = 0; i < 4; i++) rq[i] = Qs[(tr * 4 + i) * TPAD + kk];
            #pragma unroll
            for (int j = 0; j < 4; j++) rk[j] = Ks[(tc * 4 + j) * TPAD + kk];
            #pragma unroll
            for (int i = 0; i < 4; i++)
                #pragma unroll
                for (int j = 0; j < 4; j++)
                    s[i][j] = fmaf(rq[i], rk[j], s[i][j]);
        }

        const float scale = 0.125f;
        const bool diag = (kt == qt);
        #pragma unroll
        for (int i = 0; i < 4; i++)
            #pragma unroll
            for (int j = 0; j < 4; j++) {
                s[i][j] *= scale;
                if (diag && (tc * 4 + j > tr * 4 + i)) s[i][j] = -1e30f;
            }

        float mt[4];
        #pragma unroll
        for (int i = 0; i < 4; i++) {
            mt[i] = fmaxf(fmaxf(s[i][0], s[i][1]), fmaxf(s[i][2], s[i][3]));
            #pragma unroll
            for (int off = 8; off >= 1; off >>= 1)
                mt[i] = fmaxf(mt[i], __shfl_xor_sync(0xffffffffu, mt[i], off, 16));
        }

        float corr[4], ls[4];
        #pragma unroll
        for (int i = 0; i < 4; i++) {
            const float m_new = fmaxf(m_i[i], mt[i]);
            corr[i] = __expf(m_i[i] - m_new);
            m_i[i]  = m_new;
            ls[i]   = 0.0f;
            #pragma unroll
            for (int j = 0; j < 4; j++) {
                const float p = __expf(s[i][j] - m_new);
                s[i][j] = p;
                ls[i]  += p;
            }
            #pragma unroll
            for (int off = 8; off >= 1; off >>= 1)
                ls[i] += __shfl_xor_sync(0xffffffffu, ls[i], off, 16);
            l_i[i] = l_i[i] * corr[i] + ls[i];
            #pragma unroll
            for (int j = 0; j < 4; j++) O[i][j] *= corr[i];
        }

        #pragma unroll
        for (int i = 0; i < 4; i++)
            #pragma unroll
            for (int j = 0; j < 4; j++)
                Ps[(tr * 4 + i) * TPAD + tc * 4 + j] = s[i][j];
        __syncthreads();

        #pragma unroll 16
        for (int kk = 0; kk < 64; kk++) {
            float rp[4], rv[4];
            #pragma unroll
            for (int i = 0; i < 4; i++) rp[i] = Ps[(tr * 4 + i) * TPAD + kk];
            #pragma unroll
            for (int j = 0; j < 4; j++) rv[j] = Vs[kk * TPAD + tc * 4 + j];
            #pragma unroll
            for (int i = 0; i < 4; i++)
                #pragma unroll
                for (int j = 0; j < 4; j++)
                    O[i][j] = fmaf(rp[i], rv[j], O[i][j]);
        }
    }

    const int b = bh / NHEAD;
    const int h = bh % NHEAD;
    #pragma unroll
    for (int i = 0; i < 4; i++) {
        const float inv = 1.0f / l_i[i];
        const int srow = qBase + tr * 4 + i;
        #pragma unroll
        for (int j = 0; j < 4; j++)
            ctx[(b * SEQ + srow) * DMODEL + h * HDIM + tc * 4 + j] = O[i][j] * inv;
    }
}

// ---------------------------------------------------------------------------
// Launch
// ---------------------------------------------------------------------------
extern "C" void kernel_launch(void* const* d_in, const int* in_sizes, int n_in,
                              void* d_out, int out_size)
{
    const float* x  = (const float*)d_in[0];
    const float* wq = (const float*)d_in[1];
    const float* bq = (const float*)d_in[2];
    const float* wk = (const float*)d_in[3];
    const float* bk = (const float*)d_in[4];
    const float* wv = (const float*)d_in[5];
    const float* bv = (const float*)d_in[6];
    const float* wo = (const float*)d_in[7];
    const float* bo = (const float*)d_in[8];
    float* out = (float*)d_out;

    float *qp, *kp, *vp, *cp;
    __nv_bfloat16 *xh, *xl, *ch, *cl, *wh, *wl;
    cudaGetSymbolAddress((void**)&qp, g_q);
    cudaGetSymbolAddress((void**)&kp, g_k);
    cudaGetSymbolAddress((void**)&vp, g_v);
    cudaGetSymbolAddress((void**)&cp, g_ctx);
    cudaGetSymbolAddress((void**)&xh, g_xh);
    cudaGetSymbolAddress((void**)&xl, g_xl);
    cudaGetSymbolAddress((void**)&ch, g_ch);
    cudaGetSymbolAddress((void**)&cl, g_cl);
    cudaGetSymbolAddress((void**)&wh, g_wh);
    cudaGetSymbolAddress((void**)&wl, g_wl);

    const int NX = MROWS * DMODEL;           // 4194304
    const int NW = DMODEL * DMODEL;          // 1048576
    const float* wsrc[4] = {wq, wk, wv, wo};

    // Split x and weights to bf16 hi/lo
    split_bf16_kernel<<<NX / 4 / 256, 256>>>(x, xh, xl, NX);
    for (int i = 0; i < 4; i++)
        split_bf16_kernel<<<NW / 4 / 256, 256>>>(wsrc[i], wh + (size_t)i * NW,
                                                 wl + (size_t)i * NW, NW);

    cudaFuncSetAttribute(mma_gemm<0>, cudaFuncAttributeMaxDynamicSharedMemorySize, GEMM_SMEM);
    cudaFuncSetAttribute(mma_gemm<1>, cudaFuncAttributeMaxDynamicSharedMemorySize, GEMM_SMEM);

    dim3 gemmGrid(DMODEL / 128, MROWS / 128);   // (8, 32)
    dim3 blk(256);

    // Q/K/V projections (warp-MMA, fused head-transpose epilogue)
    mma_gemm<1><<<gemmGrid, blk, GEMM_SMEM>>>(xh, xl, wh + 0 * (size_t)NW, wl + 0 * (size_t)NW, bq, qp);
    mma_gemm<1><<<gemmGrid, blk, GEMM_SMEM>>>(xh, xl, wh + 1 * (size_t)NW, wl + 1 * (size_t)NW, bk, kp);
    mma_gemm<1><<<gemmGrid, blk, GEMM_SMEM>>>(xh, xl, wh + 2 * (size_t)NW, wl + 2 * (size_t)NW, bv, vp);

    // Attention (fp32 SIMT)
    const int smemBytes = 4 * 64 * TPAD * sizeof(float);   // 66560
    cudaFuncSetAttribute(attn_kernel, cudaFuncAttributeMaxDynamicSharedMemorySize, smemBytes);
    dim3 attnGrid(SEQ / 64, BATCH * NHEAD);
    attn_kernel<<<attnGrid, blk, smemBytes>>>(cp);

    // ctx -> bf16 hi/lo, then output projection
    split_bf16_kernel<<<NX / 4 / 256, 256>>>(cp, ch, cl, NX);
    mma_gemm<0><<<gemmGrid, blk, GEMM_SMEM>>>(ch, cl, wh + 3 * (size_t)NW, wl + 3 * (size_t)NW, bo, out);
}

// round 5
// speedup vs baseline: 2.7525x; 1.7570x over previous
#include <cuda_runtime.h>
#include <cuda_bf16.h>
#include <cstdint>

#define BATCH  2
#define SEQ    2048
#define DMODEL 1024
#define NHEAD  16
#define HDIM   64
#define MROWS  (BATCH * SEQ)       // 4096

// ---------------------------------------------------------------------------
// Scratch (allocation-free rule: __device__ globals)
// ---------------------------------------------------------------------------
__device__ __nv_bfloat16 g_xh[MROWS * DMODEL];      // x split hi/lo
__device__ __nv_bfloat16 g_xl[MROWS * DMODEL];
__device__ __nv_bfloat16 g_wh[4][DMODEL * DMODEL];  // wq,wk,wv,wo hi
__device__ __nv_bfloat16 g_wl[4][DMODEL * DMODEL];  // wq,wk,wv,wo lo
// q/k split, [b*NHEAD+h][s][hd]; q pre-scaled by 0.125
__device__ __nv_bfloat16 g_qh[MROWS * DMODEL];
__device__ __nv_bfloat16 g_ql[MROWS * DMODEL];
__device__ __nv_bfloat16 g_kh[MROWS * DMODEL];
__device__ __nv_bfloat16 g_kl[MROWS * DMODEL];
// v split TRANSPOSED: [b*NHEAD+h][hd][s]
__device__ __nv_bfloat16 g_vh[MROWS * DMODEL];
__device__ __nv_bfloat16 g_vl[MROWS * DMODEL];
// ctx split, [b*s][d]
__device__ __nv_bfloat16 g_ch[MROWS * DMODEL];
__device__ __nv_bfloat16 g_cl[MROWS * DMODEL];

// ---------------------------------------------------------------------------
// Warp-MMA helpers (mma.sync / ldmatrix — base compute_103 PTX)
// ---------------------------------------------------------------------------
__device__ __forceinline__ uint32_t smem_u32(const void* p) {
    uint32_t a;
    asm("{ .reg .u64 t; cvta.to.shared.u64 t, %1; cvt.u32.u64 %0, t; }"
        : "=r"(a) : "l"(p));
    return a;
}

__device__ __forceinline__ void ldmatrix_x4(uint32_t* r, uint32_t addr) {
    asm volatile("ldmatrix.sync.aligned.m8n8.x4.shared.b16 {%0,%1,%2,%3}, [%4];"
                 : "=r"(r[0]), "=r"(r[1]), "=r"(r[2]), "=r"(r[3]) : "r"(addr));
}

__device__ __forceinline__ void ldmatrix_x2(uint32_t* r, uint32_t addr) {
    asm volatile("ldmatrix.sync.aligned.m8n8.x2.shared.b16 {%0,%1}, [%2];"
                 : "=r"(r[0]), "=r"(r[1]) : "r"(addr));
}

__device__ __forceinline__ void mma_bf16(float* c, const uint32_t* a, const uint32_t* b) {
    asm volatile(
        "mma.sync.aligned.m16n8k16.row.col.f32.bf16.bf16.f32 "
        "{%0,%1,%2,%3}, {%4,%5,%6,%7}, {%8,%9}, {%0,%1,%2,%3};"
        : "+f"(c[0]), "+f"(c[1]), "+f"(c[2]), "+f"(c[3])
        : "r"(a[0]), "r"(a[1]), "r"(a[2]), "r"(a[3]), "r"(b[0]), "r"(b[1]));
}

__device__ __forceinline__ void split2(float v, __nv_bfloat16& h, __nv_bfloat16& l) {
    h = __float2bfloat16(v);
    l = __float2bfloat16(v - __bfloat162float(h));
}

// ---------------------------------------------------------------------------
// fp32 -> (bf16 hi, bf16 lo) split (x and weights only)
// ---------------------------------------------------------------------------
__global__ __launch_bounds__(256)
void split_bf16_kernel(const float* __restrict__ in,
                       __nv_bfloat16* __restrict__ hi,
                       __nv_bfloat16* __restrict__ lo, int n)
{
    int i4 = (blockIdx.x * blockDim.x + threadIdx.x) * 4;
    if (i4 >= n) return;
    float4 f = *reinterpret_cast<const float4*>(in + i4);
    float fs[4] = {f.x, f.y, f.z, f.w};
    __nv_bfloat162 hv[2], lv[2];
    #pragma unroll
    for (int j = 0; j < 2; j++) {
        __nv_bfloat16 h0, h1, l0, l1;
        split2(fs[2 * j], h0, l0);
        split2(fs[2 * j + 1], h1, l1);
        hv[j].x = h0; hv[j].y = h1;
        lv[j].x = l0; lv[j].y = l1;
    }
    *reinterpret_cast<__nv_bfloat162*>(hi + i4)     = hv[0];
    *reinterpret_cast<__nv_bfloat162*>(hi + i4 + 2) = hv[1];
    *reinterpret_cast<__nv_bfloat162*>(lo + i4)     = lv[0];
    *reinterpret_cast<__nv_bfloat162*>(lo + i4 + 2) = lv[1];
}

// ---------------------------------------------------------------------------
// Warp-MMA GEMM: C[M,N] = A[M,K] @ W[N,K]^T + bias  (split-bf16, fp32 accum)
// CTA 128x128 tile, 8 warps (2x4), warp tile 64x32, K-chunk 64.
// MODE 0: fp32 out[m*DMODEL + n]
// MODE 1: bf16 hi/lo at [((b*NHEAD+h)*SEQ + s)*HDIM + hd], scaled  (Q/K)
// MODE 2: bf16 hi/lo at [((b*NHEAD+h)*HDIM + hd)*SEQ + s]          (V^T)
// ---------------------------------------------------------------------------
#define LDT       72
#define TILE_ELEM (128 * LDT)
#define TILE_B    (TILE_ELEM * 2)        // 18432 bytes
#define GEMM_SMEM (4 * TILE_B)           // 73728 bytes

template <int MODE>
__global__ __launch_bounds__(256)
void mma_gemm(const __nv_bfloat16* __restrict__ Ah,
              const __nv_bfloat16* __restrict__ Al,
              const __nv_bfloat16* __restrict__ Bh,
              const __nv_bfloat16* __restrict__ Bl,
              const float* __restrict__ bias,
              float* __restrict__ out,
              __nv_bfloat16* __restrict__ outH,
              __nv_bfloat16* __restrict__ outL,
              float scale)
{
    extern __shared__ __align__(16) char smem[];
    __nv_bfloat16* sT = reinterpret_cast<__nv_bfloat16*>(smem);
    const uint32_t sbase = smem_u32(smem);

    const int tid  = threadIdx.x;
    const int wid  = tid >> 5;
    const int lane = tid & 31;
    const int mBase = blockIdx.y * 128;
    const int nBase = blockIdx.x * 128;
    const int warp_m = (wid >> 2) * 64;
    const int warp_n = (wid & 3) * 32;

    float acc[4][4][4];
    #pragma unroll
    for (int mi = 0; mi < 4; mi++)
        #pragma unroll
        for (int ni = 0; ni < 4; ni++)
            #pragma unroll
            for (int e = 0; e < 4; e++) acc[mi][ni][e] = 0.0f;

    const uint32_t aRow = (uint32_t)(warp_m + (lane & 15)) * LDT + (lane >> 4) * 8;
    const uint32_t bRow = (uint32_t)(warp_n + (lane & 7)) * LDT + ((lane >> 3) & 1) * 8;
    const uint32_t uA = sbase + 2 * aRow;
    const uint32_t uB = sbase + (uint32_t)(2 * TILE_B) + 2 * bRow;

    for (int kc = 0; kc < DMODEL; kc += 64) {
        __syncthreads();
        #pragma unroll
        for (int t = 0; t < 4; t++) {
            const __nv_bfloat16* src = (t == 0) ? Ah : (t == 1) ? Al : (t == 2) ? Bh : Bl;
            const int rb = (t < 2) ? mBase : nBase;
            __nv_bfloat16* dst = sT + t * TILE_ELEM;
            #pragma unroll
            for (int it = 0; it < 4; it++) {
                const int slot = tid + it * 256;
                const int row  = slot >> 3;
                const int c8   = slot & 7;
                uint4 v = *reinterpret_cast<const uint4*>(
                    src + (size_t)(rb + row) * DMODEL + kc + c8 * 8);
                *reinterpret_cast<uint4*>(dst + row * LDT + c8 * 8) = v;
            }
        }
        __syncthreads();

        #pragma unroll
        for (int ks = 0; ks < 4; ks++) {
            const uint32_t kOff = 2 * (uint32_t)(ks * 16);
            uint32_t ah[4][4], al[4][4], bh[4][2], bl[4][2];
            #pragma unroll
            for (int mi = 0; mi < 4; mi++) {
                const uint32_t addr = uA + kOff + 2 * (uint32_t)(mi * 16) * LDT;
                ldmatrix_x4(ah[mi], addr);
                ldmatrix_x4(al[mi], addr + TILE_B);
            }
            #pragma unroll
            for (int ni = 0; ni < 4; ni++) {
                const uint32_t addr = uB + kOff + 2 * (uint32_t)(ni * 8) * LDT;
                ldmatrix_x2(bh[ni], addr);
                ldmatrix_x2(bl[ni], addr + TILE_B);
            }
            #pragma unroll
            for (int mi = 0; mi < 4; mi++)
                #pragma unroll
                for (int ni = 0; ni < 4; ni++) {
                    mma_bf16(acc[mi][ni], ah[mi], bh[ni]);
                    mma_bf16(acc[mi][ni], al[mi], bh[ni]);
                    mma_bf16(acc[mi][ni], ah[mi], bl[ni]);
                }
        }
    }

    const int rBase = mBase + warp_m + (lane >> 2);
    const int cBase = nBase + warp_n + (lane & 3) * 2;
    #pragma unroll
    for (int mi = 0; mi < 4; mi++) {
        #pragma unroll
        for (int ni = 0; ni < 4; ni++) {
            #pragma unroll
            for (int half = 0; half < 2; half++) {
                const int m = rBase + mi * 16 + half * 8;
                const int n = cBase + ni * 8;
                if (MODE == 0) {
                    out[(size_t)m * DMODEL + n]     = acc[mi][ni][half * 2]     + bias[n];
                    out[(size_t)m * DMODEL + n + 1] = acc[mi][ni][half * 2 + 1] + bias[n + 1];
                } else {
                    const float v0 = (acc[mi][ni][half * 2]     + bias[n])     * scale;
                    const float v1 = (acc[mi][ni][half * 2 + 1] + bias[n + 1]) * scale;
                    const int b  = m >> 11;
                    const int s  = m & 2047;
                    const int h  = n >> 6;
                    const int hd = n & 63;
                    if (MODE == 1) {
                        const size_t idx = (((size_t)(b * NHEAD + h) * SEQ) + s) * HDIM + hd;
                        __nv_bfloat162 hv, lv;
                        split2(v0, hv.x, lv.x);
                        split2(v1, hv.y, lv.y);
                        *reinterpret_cast<__nv_bfloat162*>(outH + idx) = hv;
                        *reinterpret_cast<__nv_bfloat162*>(outL + idx) = lv;
                    } else {
                        // MODE 2: V^T layout [bh][hd][s]
                        const size_t idx = (((size_t)(b * NHEAD + h) * HDIM) + hd) * SEQ + s;
                        __nv_bfloat16 h0, l0, h1, l1;
                        split2(v0, h0, l0);
                        split2(v1, h1, l1);
                        outH[idx]       = h0;
                        outL[idx]       = l0;
                        outH[idx + SEQ] = h1;   // hd+1 row
                        outL[idx + SEQ] = l1;
                    }
                }
            }
        }
    }
}

// ---------------------------------------------------------------------------
// Tensor-core flash attention (causal), split-bf16, fp32 softmax.
// grid = (SEQ/64, BATCH*NHEAD), 128 threads (4 warps; warp owns 16 q-rows).
// Q pre-scaled by 0.125. V consumed pre-transposed [bh][hd][s].
// P round-trips through smem; all ldmatrix patterns identical to mma_gemm.
// ---------------------------------------------------------------------------
#define ALDT 72

__global__ __launch_bounds__(128)
void attn_mma_kernel()
{
    __shared__ __align__(16) __nv_bfloat16 sA[64 * ALDT];   // Q-hi / K-hi / P-hi
    __shared__ __align__(16) __nv_bfloat16 sB[64 * ALDT];   // Q-lo / K-lo / P-lo
    __shared__ __align__(16) __nv_bfloat16 sVh[64 * ALDT];  // V^T hi [hd][kv]
    __shared__ __align__(16) __nv_bfloat16 sVl[64 * ALDT];  // V^T lo

    const int tid  = threadIdx.x;
    const int w    = tid >> 5;
    const int lane = tid & 31;
    const int qt   = gridDim.x - 1 - blockIdx.x;    // long CTAs first
    const int bh   = blockIdx.y;
    const int qBase = qt * 64;
    const size_t hOff = (size_t)bh * SEQ * HDIM;    // q,k: [bh][s][hd]
    const size_t vOff = (size_t)bh * HDIM * SEQ;    // v^T: [bh][hd][s]

    const uint32_t uA  = smem_u32(sA);
    const uint32_t uB  = smem_u32(sB);
    const uint32_t uVh = smem_u32(sVh);
    const uint32_t uVl = smem_u32(sVl);

    // --- Stage Q tile into sA/sB, pull A-fragments to registers (R3 pattern) ---
    #pragma unroll
    for (int it = 0; it < 4; it++) {
        const int slot = tid + it * 128;          // 0..511
        const int row = slot >> 3, c8 = slot & 7;
        const size_t g = hOff + (size_t)(qBase + row) * HDIM + c8 * 8;
        *reinterpret_cast<uint4*>(sA + row * ALDT + c8 * 8) =
            *reinterpret_cast<const uint4*>(g_qh + g);
        *reinterpret_cast<uint4*>(sB + row * ALDT + c8 * 8) =
            *reinterpret_cast<const uint4*>(g_ql + g);
    }
    __syncthreads();

    uint32_t qh[4][4], ql[4][4];
    {
        const uint32_t qa = 2 * ((uint32_t)(w * 16 + (lane & 15)) * ALDT + (lane >> 4) * 8);
        #pragma unroll
        for (int t = 0; t < 4; t++) {
            ldmatrix_x4(qh[t], uA + qa + 32 * t);
            ldmatrix_x4(ql[t], uB + qa + 32 * t);
        }
    }

    float O[8][4];
    #pragma unroll
    for (int j = 0; j < 8; j++)
        #pragma unroll
        for (int e = 0; e < 4; e++) O[j][e] = 0.0f;
    float m0 = -1e30f, m1 = -1e30f, l0 = 0.0f, l1 = 0.0f;

    for (int kt = 0; kt <= qt; kt++) {
        const int kBase = kt * 64;
        __syncthreads();   // previous readers of sA/sB/sV done

        // --- Load K (hi/lo) and V^T (hi/lo) tiles ---
        #pragma unroll
        for (int it = 0; it < 4; it++) {
            const int slot = tid + it * 128;
            const int row = slot >> 3, c8 = slot & 7;
            const uint32_t so = row * ALDT + c8 * 8;
            const size_t gk = hOff + (size_t)(kBase + row) * HDIM + c8 * 8;
            *reinterpret_cast<uint4*>(sA + so) = *reinterpret_cast<const uint4*>(g_kh + gk);
            *reinterpret_cast<uint4*>(sB + so) = *reinterpret_cast<const uint4*>(g_kl + gk);
            const size_t gv = vOff + (size_t)row * SEQ + kBase + c8 * 8;   // row = hd
            *reinterpret_cast<uint4*>(sVh + so) = *reinterpret_cast<const uint4*>(g_vh + gv);
            *reinterpret_cast<uint4*>(sVl + so) = *reinterpret_cast<const uint4*>(g_vl + gv);
        }
        __syncthreads();

        // --- S = Q K^T (split: hh + lh + hl); B-frags via R3's x2 pattern ---
        float s[8][4];
        #pragma unroll
        for (int j = 0; j < 8; j++)
            #pragma unroll
            for (int e = 0; e < 4; e++) s[j][e] = 0.0f;

        #pragma unroll
        for (int t = 0; t < 4; t++) {
            #pragma unroll
            for (int nf = 0; nf < 8; nf++) {
                const uint32_t ba = 2 * ((uint32_t)(nf * 8 + (lane & 7)) * ALDT
                                         + 16 * t + 8 * ((lane >> 3) & 1));
                uint32_t kh2[2], kl2[2];
                ldmatrix_x2(kh2, uA + ba);
                ldmatrix_x2(kl2, uB + ba);
                mma_bf16(s[nf], qh[t], kh2);
                mma_bf16(s[nf], ql[t], kh2);
                mma_bf16(s[nf], qh[t], kl2);
            }
        }

        // --- Causal mask on diagonal tile (accumulator layout per R3 epilogue) ---
        const int rl0 = w * 16 + (lane >> 2);     // local row 0
        const int c0  = 2 * (lane & 3);
        if (kt == qt) {
            #pragma unroll
            for (int j = 0; j < 8; j++) {
                #pragma unroll
                for (int e = 0; e < 2; e++) {
                    const int col = 8 * j + c0 + e;
                    if (col > rl0)     s[j][e]     = -1e30f;
                    if (col > rl0 + 8) s[j][2 + e] = -1e30f;
                }
            }
        }

        // --- Online softmax (rows rl0 and rl0+8; 4 lanes share a row) ---
        float mt0 = -1e30f, mt1 = -1e30f;
        #pragma unroll
        for (int j = 0; j < 8; j++) {
            mt0 = fmaxf(mt0, fmaxf(s[j][0], s[j][1]));
            mt1 = fmaxf(mt1, fmaxf(s[j][2], s[j][3]));
        }
        mt0 = fmaxf(mt0, __shfl_xor_sync(0xffffffffu, mt0, 1));
        mt0 = fmaxf(mt0, __shfl_xor_sync(0xffffffffu, mt0, 2));
        mt1 = fmaxf(mt1, __shfl_xor_sync(0xffffffffu, mt1, 1));
        mt1 = fmaxf(mt1, __shfl_xor_sync(0xffffffffu, mt1, 2));

        const float mn0 = fmaxf(m0, mt0);
        const float mn1 = fmaxf(m1, mt1);
        const float cr0 = __expf(m0 - mn0);
        const float cr1 = __expf(m1 - mn1);
        m0 = mn0; m1 = mn1;

        float ls0 = 0.0f, ls1 = 0.0f;
        #pragma unroll
        for (int j = 0; j < 8; j++) {
            s[j][0] = __expf(s[j][0] - mn0);
            s[j][1] = __expf(s[j][1] - mn0);
            s[j][2] = __expf(s[j][2] - mn1);
            s[j][3] = __expf(s[j][3] - mn1);
            ls0 += s[j][0] + s[j][1];
            ls1 += s[j][2] + s[j][3];
        }
        ls0 += __shfl_xor_sync(0xffffffffu, ls0, 1);
        ls0 += __shfl_xor_sync(0xffffffffu, ls0, 2);
        ls1 += __shfl_xor_sync(0xffffffffu, ls1, 1);
        ls1 += __shfl_xor_sync(0xffffffffu, ls1, 2);
        l0 = l0 * cr0 + ls0;
        l1 = l1 * cr1 + ls1;
        #pragma unroll
        for (int j = 0; j < 8; j++) {
            O[j][0] *= cr0; O[j][1] *= cr0;
            O[j][2] *= cr1; O[j][3] *= cr1;
        }

        // --- Store P (split hi/lo) into sA/sB (K is dead after barrier) ---
        __syncthreads();
        #pragma unroll
        for (int j = 0; j < 8; j++) {
            const int col = 8 * j + c0;
            __nv_bfloat162 hv, lv;
            split2(s[j][0], hv.x, lv.x);
            split2(s[j][1], hv.y, lv.y);
            *reinterpret_cast<__nv_bfloat162*>(sA + rl0 * ALDT + col) = hv;
            *reinterpret_cast<__nv_bfloat162*>(sB + rl0 * ALDT + col) = lv;
            split2(s[j][2], hv.x, lv.x);
            split2(s[j][3], hv.y, lv.y);
            *reinterpret_cast<__nv_bfloat162*>(sA + (rl0 + 8) * ALDT + col) = hv;
            *reinterpret_cast<__nv_bfloat162*>(sB + (rl0 + 8) * ALDT + col) = lv;
        }
        __syncthreads();

        // --- O += P V : A-frags (P) via R3 x4 pattern, B-frags (V^T) via x2 ---
        const uint32_t pa = 2 * ((uint32_t)(w * 16 + (lane & 15)) * ALDT + (lane >> 4) * 8);
        #pragma unroll
        for (int t = 0; t < 4; t++) {
            uint32_t ph4[4], pl4[4];
            ldmatrix_x4(ph4, uA + pa + 32 * t);
            ldmatrix_x4(pl4, uB + pa + 32 * t);
            #pragma unroll
            for (int hf = 0; hf < 8; hf++) {
                const uint32_t va = 2 * ((uint32_t)(hf * 8 + (lane & 7)) * ALDT
                                         + 16 * t + 8 * ((lane >> 3) & 1));
                uint32_t vh2[2], vl2[2];
                ldmatrix_x2(vh2, uVh + va);
                ldmatrix_x2(vl2, uVl + va);
                mma_bf16(O[hf], ph4, vh2);
                mma_bf16(O[hf], pl4, vh2);
                mma_bf16(O[hf], ph4, vl2);
            }
        }
    }

    // --- Epilogue: ctx hi/lo to [b*SEQ+s][DMODEL] ---
    const float inv0 = 1.0f / l0;
    const float inv1 = 1.0f / l1;
    const int b    = bh >> 4;
    const int head = bh & 15;
    const int r0   = qBase + w * 16 + (lane >> 2);
    #pragma unroll
    for (int j = 0; j < 8; j++) {
        const int col = head * HDIM + 8 * j + 2 * (lane & 3);
        const size_t i0 = (size_t)(b * SEQ + r0) * DMODEL + col;
        const size_t i1 = (size_t)(b * SEQ + r0 + 8) * DMODEL + col;
        __nv_bfloat162 hv, lv;
        split2(O[j][0] * inv0, hv.x, lv.x);
        split2(O[j][1] * inv0, hv.y, lv.y);
        *reinterpret_cast<__nv_bfloat162*>(g_ch + i0) = hv;
        *reinterpret_cast<__nv_bfloat162*>(g_cl + i0) = lv;
        split2(O[j][2] * inv1, hv.x, lv.x);
        split2(O[j][3] * inv1, hv.y, lv.y);
        *reinterpret_cast<__nv_bfloat162*>(g_ch + i1) = hv;
        *reinterpret_cast<__nv_bfloat162*>(g_cl + i1) = lv;
    }
}

// ---------------------------------------------------------------------------
// Launch
// ---------------------------------------------------------------------------
extern "C" void kernel_launch(void* const* d_in, const int* in_sizes, int n_in,
                              void* d_out, int out_size)
{
    const float* x  = (const float*)d_in[0];
    const float* wq = (const float*)d_in[1];
    const float* bq = (const float*)d_in[2];
    const float* wk = (const float*)d_in[3];
    const float* bk = (const float*)d_in[4];
    const float* wv = (const float*)d_in[5];
    const float* bv = (const float*)d_in[6];
    const float* wo = (const float*)d_in[7];
    const float* bo = (const float*)d_in[8];
    float* out = (float*)d_out;

    __nv_bfloat16 *xh, *xl, *wh, *wl, *qh, *ql, *kh, *kl, *vh, *vl, *ch, *cl;
    cudaGetSymbolAddress((void**)&xh, g_xh);
    cudaGetSymbolAddress((void**)&xl, g_xl);
    cudaGetSymbolAddress((void**)&wh, g_wh);
    cudaGetSymbolAddress((void**)&wl, g_wl);
    cudaGetSymbolAddress((void**)&qh, g_qh);
    cudaGetSymbolAddress((void**)&ql, g_ql);
    cudaGetSymbolAddress((void**)&kh, g_kh);
    cudaGetSymbolAddress((void**)&kl, g_kl);
    cudaGetSymbolAddress((void**)&vh, g_vh);
    cudaGetSymbolAddress((void**)&vl, g_vl);
    cudaGetSymbolAddress((void**)&ch, g_ch);
    cudaGetSymbolAddress((void**)&cl, g_cl);

    const int NX = MROWS * DMODEL;
    const int NW = DMODEL * DMODEL;
    const float* wsrc[4] = {wq, wk, wv, wo};

    split_bf16_kernel<<<NX / 4 / 256, 256>>>(x, xh, xl, NX);
    for (int i = 0; i < 4; i++)
        split_bf16_kernel<<<NW / 4 / 256, 256>>>(wsrc[i], wh + (size_t)i * NW,
                                                 wl + (size_t)i * NW, NW);

    cudaFuncSetAttribute(mma_gemm<0>, cudaFuncAttributeMaxDynamicSharedMemorySize, GEMM_SMEM);
    cudaFuncSetAttribute(mma_gemm<1>, cudaFuncAttributeMaxDynamicSharedMemorySize, GEMM_SMEM);
    cudaFuncSetAttribute(mma_gemm<2>, cudaFuncAttributeMaxDynamicSharedMemorySize, GEMM_SMEM);

    dim3 gemmGrid(DMODEL / 128, MROWS / 128);
    dim3 blk(256);

    // Q/K projections -> split bf16 [bh][s][hd]; Q scaled by 0.125
    mma_gemm<1><<<gemmGrid, blk, GEMM_SMEM>>>(xh, xl, wh + 0 * (size_t)NW, wl + 0 * (size_t)NW,
                                              bq, nullptr, qh, ql, 0.125f);
    mma_gemm<1><<<gemmGrid, blk, GEMM_SMEM>>>(xh, xl, wh + 1 * (size_t)NW, wl + 1 * (size_t)NW,
                                              bk, nullptr, kh, kl, 1.0f);
    // V projection -> split bf16 TRANSPOSED [bh][hd][s]
    mma_gemm<2><<<gemmGrid, blk, GEMM_SMEM>>>(xh, xl, wh + 2 * (size_t)NW, wl + 2 * (size_t)NW,
                                              bv, nullptr, vh, vl, 1.0f);

    // Tensor-core flash attention
    dim3 attnGrid(SEQ / 64, BATCH * NHEAD);
    attn_mma_kernel<<<attnGrid, 128>>>();

    // Output projection (fp32 out)
    mma_gemm<0><<<gemmGrid, blk, GEMM_SMEM>>>(ch, cl, wh + 3 * (size_t)NW, wl + 3 * (size_t)NW,
                                              bo, out, nullptr, nullptr, 1.0f);
}

// round 6
// speedup vs baseline: 3.0504x; 1.1082x over previous
#include <cuda_runtime.h>
#include <cuda_bf16.h>
#include <cstdint>

#define BATCH  2
#define SEQ    2048
#define DMODEL 1024
#define NHEAD  16
#define HDIM   64
#define MROWS  (BATCH * SEQ)       // 4096

// ---------------------------------------------------------------------------
// Scratch (allocation-free rule: __device__ globals)
// ---------------------------------------------------------------------------
__device__ __nv_bfloat16 g_xh[MROWS * DMODEL];      // x split hi/lo
__device__ __nv_bfloat16 g_xl[MROWS * DMODEL];
__device__ __nv_bfloat16 g_wh[4][DMODEL * DMODEL];  // wq,wk,wv,wo hi
__device__ __nv_bfloat16 g_wl[4][DMODEL * DMODEL];  // wq,wk,wv,wo lo
// q/k split, [b*NHEAD+h][s][hd]; q pre-scaled by 0.125
__device__ __nv_bfloat16 g_qh[MROWS * DMODEL];
__device__ __nv_bfloat16 g_ql[MROWS * DMODEL];
__device__ __nv_bfloat16 g_kh[MROWS * DMODEL];
__device__ __nv_bfloat16 g_kl[MROWS * DMODEL];
// v split TRANSPOSED: [b*NHEAD+h][hd][s]
__device__ __nv_bfloat16 g_vh[MROWS * DMODEL];
__device__ __nv_bfloat16 g_vl[MROWS * DMODEL];
// ctx split, [b*s][d]
__device__ __nv_bfloat16 g_ch[MROWS * DMODEL];
__device__ __nv_bfloat16 g_cl[MROWS * DMODEL];

// ---------------------------------------------------------------------------
// Warp-MMA + cp.async helpers (base compute_103 PTX)
// ---------------------------------------------------------------------------
__device__ __forceinline__ uint32_t smem_u32(const void* p) {
    uint32_t a;
    asm("{ .reg .u64 t; cvta.to.shared.u64 t, %1; cvt.u32.u64 %0, t; }"
        : "=r"(a) : "l"(p));
    return a;
}

__device__ __forceinline__ void ldmatrix_x4(uint32_t* r, uint32_t addr) {
    asm volatile("ldmatrix.sync.aligned.m8n8.x4.shared.b16 {%0,%1,%2,%3}, [%4];"
                 : "=r"(r[0]), "=r"(r[1]), "=r"(r[2]), "=r"(r[3]) : "r"(addr));
}

__device__ __forceinline__ void ldmatrix_x2(uint32_t* r, uint32_t addr) {
    asm volatile("ldmatrix.sync.aligned.m8n8.x2.shared.b16 {%0,%1}, [%2];"
                 : "=r"(r[0]), "=r"(r[1]) : "r"(addr));
}

__device__ __forceinline__ void mma_bf16(float* c, const uint32_t* a, const uint32_t* b) {
    asm volatile(
        "mma.sync.aligned.m16n8k16.row.col.f32.bf16.bf16.f32 "
        "{%0,%1,%2,%3}, {%4,%5,%6,%7}, {%8,%9}, {%0,%1,%2,%3};"
        : "+f"(c[0]), "+f"(c[1]), "+f"(c[2]), "+f"(c[3])
        : "r"(a[0]), "r"(a[1]), "r"(a[2]), "r"(a[3]), "r"(b[0]), "r"(b[1]));
}

__device__ __forceinline__ void cp_async16(uint32_t dst, const void* src) {
    asm volatile("cp.async.cg.shared.global [%0], [%1], 16;" :: "r"(dst), "l"(src));
}
#define CP_COMMIT() asm volatile("cp.async.commit_group;" ::: "memory")
#define CP_WAIT0()  asm volatile("cp.async.wait_group 0;" ::: "memory")

__device__ __forceinline__ void split2(float v, __nv_bfloat16& h, __nv_bfloat16& l) {
    h = __float2bfloat16(v);
    l = __float2bfloat16(v - __bfloat162float(h));
}

// ---------------------------------------------------------------------------
// fp32 -> (bf16 hi, bf16 lo) split (x and weights only)
// ---------------------------------------------------------------------------
__global__ __launch_bounds__(256)
void split_bf16_kernel(const float* __restrict__ in,
                       __nv_bfloat16* __restrict__ hi,
                       __nv_bfloat16* __restrict__ lo, int n)
{
    int i4 = (blockIdx.x * blockDim.x + threadIdx.x) * 4;
    if (i4 >= n) return;
    float4 f = *reinterpret_cast<const float4*>(in + i4);
    float fs[4] = {f.x, f.y, f.z, f.w};
    __nv_bfloat162 hv[2], lv[2];
    #pragma unroll
    for (int j = 0; j < 2; j++) {
        __nv_bfloat16 h0, h1, l0, l1;
        split2(fs[2 * j], h0, l0);
        split2(fs[2 * j + 1], h1, l1);
        hv[j].x = h0; hv[j].y = h1;
        lv[j].x = l0; lv[j].y = l1;
    }
    *reinterpret_cast<__nv_bfloat162*>(hi + i4)     = hv[0];
    *reinterpret_cast<__nv_bfloat162*>(hi + i4 + 2) = hv[1];
    *reinterpret_cast<__nv_bfloat162*>(lo + i4)     = lv[0];
    *reinterpret_cast<__nv_bfloat162*>(lo + i4 + 2) = lv[1];
}

// ---------------------------------------------------------------------------
// Warp-MMA GEMM, cp.async double-buffered.
// C[M,N] = A[M,K] @ W[N,K]^T + bias  (split-bf16, fp32 accum)
// CTA 128x128 tile, 8 warps (2x4), warp tile 64x32, K-chunk 64, 2 stages.
// MODE 0: fp32 out[m*DMODEL + n]
// MODE 1: bf16 hi/lo at [((b*NHEAD+h)*SEQ + s)*HDIM + hd], scaled  (Q/K)
// MODE 2: bf16 hi/lo at [((b*NHEAD+h)*HDIM + hd)*SEQ + s]          (V^T)
// ---------------------------------------------------------------------------
#define LDT       72
#define TILE_ELEM (128 * LDT)
#define TILE_B    (TILE_ELEM * 2)        // 18432 bytes
#define STAGE_B   (4 * TILE_B)           // 73728 bytes
#define GEMM_SMEM (2 * STAGE_B)          // 147456 bytes

template <int MODE>
__global__ __launch_bounds__(256)
void mma_gemm(const __nv_bfloat16* __restrict__ Ah,
              const __nv_bfloat16* __restrict__ Al,
              const __nv_bfloat16* __restrict__ Bh,
              const __nv_bfloat16* __restrict__ Bl,
              const float* __restrict__ bias,
              float* __restrict__ out,
              __nv_bfloat16* __restrict__ outH,
              __nv_bfloat16* __restrict__ outL,
              float scale)
{
    extern __shared__ __align__(16) char smem[];
    const uint32_t sbase = smem_u32(smem);

    const int tid  = threadIdx.x;
    const int wid  = tid >> 5;
    const int lane = tid & 31;
    const int mBase = blockIdx.y * 128;
    const int nBase = blockIdx.x * 128;
    const int warp_m = (wid >> 2) * 64;
    const int warp_n = (wid & 3) * 32;

    const __nv_bfloat16* srcs[4] = {Ah, Al, Bh, Bl};

    // stage loader: 16 cp.async per thread
    auto stage = [&](uint32_t sdst, int kc) {
        #pragma unroll
        for (int t = 0; t < 4; t++) {
            const __nv_bfloat16* src = srcs[t];
            const int rb = (t < 2) ? mBase : nBase;
            #pragma unroll
            for (int it = 0; it < 4; it++) {
                const int slot = tid + it * 256;
                const int row  = slot >> 3;
                const int c8   = slot & 7;
                cp_async16(sdst + t * TILE_B + 2 * (uint32_t)(row * LDT + c8 * 8),
                           src + (size_t)(rb + row) * DMODEL + kc + c8 * 8);
            }
        }
    };

    float acc[4][4][4];
    #pragma unroll
    for (int mi = 0; mi < 4; mi++)
        #pragma unroll
        for (int ni = 0; ni < 4; ni++)
            #pragma unroll
            for (int e = 0; e < 4; e++) acc[mi][ni][e] = 0.0f;

    const uint32_t aRow = (uint32_t)(warp_m + (lane & 15)) * LDT + (lane >> 4) * 8;
    const uint32_t bRow = (uint32_t)(warp_n + (lane & 7)) * LDT + ((lane >> 3) & 1) * 8;

    stage(sbase, 0);
    CP_COMMIT();

    int cur = 0;
    for (int kc = 0; kc < DMODEL; kc += 64) {
        CP_WAIT0();
        __syncthreads();
        if (kc + 64 < DMODEL) {
            stage(sbase + (uint32_t)((cur ^ 1) * STAGE_B), kc + 64);
            CP_COMMIT();
        }

        const uint32_t uA = sbase + (uint32_t)(cur * STAGE_B) + 2 * aRow;
        const uint32_t uB = sbase + (uint32_t)(cur * STAGE_B + 2 * TILE_B) + 2 * bRow;

        #pragma unroll
        for (int ks = 0; ks < 4; ks++) {
            const uint32_t kOff = 2 * (uint32_t)(ks * 16);
            uint32_t ah[4][4], al[4][4], bh[4][2], bl[4][2];
            #pragma unroll
            for (int mi = 0; mi < 4; mi++) {
                const uint32_t addr = uA + kOff + 2 * (uint32_t)(mi * 16) * LDT;
                ldmatrix_x4(ah[mi], addr);
                ldmatrix_x4(al[mi], addr + TILE_B);
            }
            #pragma unroll
            for (int ni = 0; ni < 4; ni++) {
                const uint32_t addr = uB + kOff + 2 * (uint32_t)(ni * 8) * LDT;
                ldmatrix_x2(bh[ni], addr);
                ldmatrix_x2(bl[ni], addr + TILE_B);
            }
            #pragma unroll
            for (int mi = 0; mi < 4; mi++)
                #pragma unroll
                for (int ni = 0; ni < 4; ni++) {
                    mma_bf16(acc[mi][ni], ah[mi], bh[ni]);
                    mma_bf16(acc[mi][ni], al[mi], bh[ni]);
                    mma_bf16(acc[mi][ni], ah[mi], bl[ni]);
                }
        }
        cur ^= 1;
    }

    const int rBase = mBase + warp_m + (lane >> 2);
    const int cBase = nBase + warp_n + (lane & 3) * 2;
    #pragma unroll
    for (int mi = 0; mi < 4; mi++) {
        #pragma unroll
        for (int ni = 0; ni < 4; ni++) {
            #pragma unroll
            for (int half = 0; half < 2; half++) {
                const int m = rBase + mi * 16 + half * 8;
                const int n = cBase + ni * 8;
                if (MODE == 0) {
                    out[(size_t)m * DMODEL + n]     = acc[mi][ni][half * 2]     + bias[n];
                    out[(size_t)m * DMODEL + n + 1] = acc[mi][ni][half * 2 + 1] + bias[n + 1];
                } else {
                    const float v0 = (acc[mi][ni][half * 2]     + bias[n])     * scale;
                    const float v1 = (acc[mi][ni][half * 2 + 1] + bias[n + 1]) * scale;
                    const int b  = m >> 11;
                    const int s  = m & 2047;
                    const int h  = n >> 6;
                    const int hd = n & 63;
                    if (MODE == 1) {
                        const size_t idx = (((size_t)(b * NHEAD + h) * SEQ) + s) * HDIM + hd;
                        __nv_bfloat162 hv, lv;
                        split2(v0, hv.x, lv.x);
                        split2(v1, hv.y, lv.y);
                        *reinterpret_cast<__nv_bfloat162*>(outH + idx) = hv;
                        *reinterpret_cast<__nv_bfloat162*>(outL + idx) = lv;
                    } else {
                        const size_t idx = (((size_t)(b * NHEAD + h) * HDIM) + hd) * SEQ + s;
                        __nv_bfloat16 h0, l0, h1, l1;
                        split2(v0, h0, l0);
                        split2(v1, h1, l1);
                        outH[idx]       = h0;
                        outL[idx]       = l0;
                        outH[idx + SEQ] = h1;
                        outL[idx + SEQ] = l1;
                    }
                }
            }
        }
    }
}

// ---------------------------------------------------------------------------
// Tensor-core flash attention (causal), split-bf16, cp.async double-buffered.
// grid = (SEQ/64, BATCH*NHEAD), 128 threads (4 warps; warp owns 16 q-rows).
// Q pre-scaled by 0.125. V consumed pre-transposed [bh][hd][s].
// Smem layout (dynamic, 92160 B):
//   stage s (s=0,1) at s*36864: Kh(9216) Kl(9216) Vh(9216) Vl(9216)
//   P at 73728: Ph(9216) Pl(9216)   (also used to stage Q initially)
// ---------------------------------------------------------------------------
#define ALDT   72
#define AT_B   9216                       // one 64x72 bf16 tile, bytes
#define AST_B  (4 * AT_B)                 // stage stride: 36864
#define P_OFF  (2 * AST_B)                // 73728
#define ATTN_SMEM (P_OFF + 2 * AT_B)      // 92160

__global__ __launch_bounds__(128)
void attn_mma_kernel()
{
    extern __shared__ __align__(16) char asmem[];
    __nv_bfloat16* sM = reinterpret_cast<__nv_bfloat16*>(asmem);
    const uint32_t abase = smem_u32(asmem);

    const int tid  = threadIdx.x;
    const int w    = tid >> 5;
    const int lane = tid & 31;
    const int qt   = gridDim.x - 1 - blockIdx.x;    // long CTAs first
    const int bh   = blockIdx.y;
    const int qBase = qt * 64;
    const size_t hOff = (size_t)bh * SEQ * HDIM;    // q,k: [bh][s][hd]
    const size_t vOff = (size_t)bh * HDIM * SEQ;    // v^T: [bh][hd][s]

    // stage loader for K/V tiles: 16 cp.async per thread
    auto stageKV = [&](uint32_t su, int kBase) {
        #pragma unroll
        for (int it = 0; it < 4; it++) {
            const int slot = tid + it * 128;
            const int row = slot >> 3, c8 = slot & 7;
            const uint32_t so = 2 * (uint32_t)(row * ALDT + c8 * 8);
            const size_t gk = hOff + (size_t)(kBase + row) * HDIM + c8 * 8;
            cp_async16(su + so,             g_kh + gk);
            cp_async16(su + AT_B + so,      g_kl + gk);
            const size_t gv = vOff + (size_t)row * SEQ + kBase + c8 * 8;
            cp_async16(su + 2 * AT_B + so,  g_vh + gv);
            cp_async16(su + 3 * AT_B + so,  g_vl + gv);
        }
    };

    // Prefetch first K/V stage
    stageKV(abase, 0);
    CP_COMMIT();

    // Stage Q through the P buffers (regular loads), pull A-frags to registers
    {
        __nv_bfloat16* sPh = sM + P_OFF / 2;
        __nv_bfloat16* sPl = sPh + AT_B / 2;
        #pragma unroll
        for (int it = 0; it < 4; it++) {
            const int slot = tid + it * 128;
            const int row = slot >> 3, c8 = slot & 7;
            const size_t g = hOff + (size_t)(qBase + row) * HDIM + c8 * 8;
            *reinterpret_cast<uint4*>(sPh + row * ALDT + c8 * 8) =
                *reinterpret_cast<const uint4*>(g_qh + g);
            *reinterpret_cast<uint4*>(sPl + row * ALDT + c8 * 8) =
                *reinterpret_cast<const uint4*>(g_ql + g);
        }
    }
    __syncthreads();

    uint32_t qh[4][4], ql[4][4];
    {
        const uint32_t qa = abase + P_OFF +
            2 * ((uint32_t)(w * 16 + (lane & 15)) * ALDT + (lane >> 4) * 8);
        #pragma unroll
        for (int t = 0; t < 4; t++) {
            ldmatrix_x4(qh[t], qa + 32 * t);
            ldmatrix_x4(ql[t], qa + AT_B + 32 * t);
        }
    }

    float O[8][4];
    #pragma unroll
    for (int j = 0; j < 8; j++)
        #pragma unroll
        for (int e = 0; e < 4; e++) O[j][e] = 0.0f;
    float m0 = -1e30f, m1 = -1e30f, l0 = 0.0f, l1 = 0.0f;

    const int rl0 = w * 16 + (lane >> 2);
    const int c0  = 2 * (lane & 3);
    const uint32_t uP  = abase + P_OFF;
    const uint32_t pa  = uP + 2 * ((uint32_t)(w * 16 + (lane & 15)) * ALDT + (lane >> 4) * 8);

    int cur = 0;
    for (int kt = 0; kt <= qt; kt++) {
        CP_WAIT0();
        __syncthreads();   // stage[cur] ready; prev readers of stage[cur^1] done
        if (kt + 1 <= qt) {
            stageKV(abase + (uint32_t)((cur ^ 1) * AST_B), (kt + 1) * 64);
            CP_COMMIT();
        }
        const uint32_t uK = abase + (uint32_t)(cur * AST_B);
        const uint32_t uV = uK + 2 * AT_B;

        // --- S = Q K^T (split: hh + lh + hl) ---
        float s[8][4];
        #pragma unroll
        for (int j = 0; j < 8; j++)
            #pragma unroll
            for (int e = 0; e < 4; e++) s[j][e] = 0.0f;

        #pragma unroll
        for (int t = 0; t < 4; t++) {
            #pragma unroll
            for (int nf = 0; nf < 8; nf++) {
                const uint32_t ba = uK + 2 * ((uint32_t)(nf * 8 + (lane & 7)) * ALDT
                                              + 16 * t + 8 * ((lane >> 3) & 1));
                uint32_t kh2[2], kl2[2];
                ldmatrix_x2(kh2, ba);
                ldmatrix_x2(kl2, ba + AT_B);
                mma_bf16(s[nf], qh[t], kh2);
                mma_bf16(s[nf], ql[t], kh2);
                mma_bf16(s[nf], qh[t], kl2);
            }
        }

        // --- Causal mask on diagonal tile ---
        if (kt == qt) {
            #pragma unroll
            for (int j = 0; j < 8; j++) {
                #pragma unroll
                for (int e = 0; e < 2; e++) {
                    const int col = 8 * j + c0 + e;
                    if (col > rl0)     s[j][e]     = -1e30f;
                    if (col > rl0 + 8) s[j][2 + e] = -1e30f;
                }
            }
        }

        // --- Online softmax ---
        float mt0 = -1e30f, mt1 = -1e30f;
        #pragma unroll
        for (int j = 0; j < 8; j++) {
            mt0 = fmaxf(mt0, fmaxf(s[j][0], s[j][1]));
            mt1 = fmaxf(mt1, fmaxf(s[j][2], s[j][3]));
        }
        mt0 = fmaxf(mt0, __shfl_xor_sync(0xffffffffu, mt0, 1));
        mt0 = fmaxf(mt0, __shfl_xor_sync(0xffffffffu, mt0, 2));
        mt1 = fmaxf(mt1, __shfl_xor_sync(0xffffffffu, mt1, 1));
        mt1 = fmaxf(mt1, __shfl_xor_sync(0xffffffffu, mt1, 2));

        const float mn0 = fmaxf(m0, mt0);
        const float mn1 = fmaxf(m1, mt1);
        const float cr0 = __expf(m0 - mn0);
        const float cr1 = __expf(m1 - mn1);
        m0 = mn0; m1 = mn1;

        float ls0 = 0.0f, ls1 = 0.0f;
        #pragma unroll
        for (int j = 0; j < 8; j++) {
            s[j][0] = __expf(s[j][0] - mn0);
            s[j][1] = __expf(s[j][1] - mn0);
            s[j][2] = __expf(s[j][2] - mn1);
            s[j][3] = __expf(s[j][3] - mn1);
            ls0 += s[j][0] + s[j][1];
            ls1 += s[j][2] + s[j][3];
        }
        ls0 += __shfl_xor_sync(0xffffffffu, ls0, 1);
        ls0 += __shfl_xor_sync(0xffffffffu, ls0, 2);
        ls1 += __shfl_xor_sync(0xffffffffu, ls1, 1);
        ls1 += __shfl_xor_sync(0xffffffffu, ls1, 2);
        l0 = l0 * cr0 + ls0;
        l1 = l1 * cr1 + ls1;
        #pragma unroll
        for (int j = 0; j < 8; j++) {
            O[j][0] *= cr0; O[j][1] *= cr0;
            O[j][2] *= cr1; O[j][3] *= cr1;
        }

        // --- Store P (hi/lo) into dedicated P buffers: same-warp rows only ---
        __nv_bfloat16* sPh = sM + P_OFF / 2;
        __nv_bfloat16* sPl = sPh + AT_B / 2;
        #pragma unroll
        for (int j = 0; j < 8; j++) {
            const int col = 8 * j + c0;
            __nv_bfloat162 hv, lv;
            split2(s[j][0], hv.x, lv.x);
            split2(s[j][1], hv.y, lv.y);
            *reinterpret_cast<__nv_bfloat162*>(sPh + rl0 * ALDT + col) = hv;
            *reinterpret_cast<__nv_bfloat162*>(sPl + rl0 * ALDT + col) = lv;
            split2(s[j][2], hv.x, lv.x);
            split2(s[j][3], hv.y, lv.y);
            *reinterpret_cast<__nv_bfloat162*>(sPh + (rl0 + 8) * ALDT + col) = hv;
            *reinterpret_cast<__nv_bfloat162*>(sPl + (rl0 + 8) * ALDT + col) = lv;
        }
        __syncwarp();

        // --- O += P V ---
        #pragma unroll
        for (int t = 0; t < 4; t++) {
            uint32_t ph4[4], pl4[4];
            ldmatrix_x4(ph4, pa + 32 * t);
            ldmatrix_x4(pl4, pa + AT_B + 32 * t);
            #pragma unroll
            for (int hf = 0; hf < 8; hf++) {
                const uint32_t va = uV + 2 * ((uint32_t)(hf * 8 + (lane & 7)) * ALDT
                                              + 16 * t + 8 * ((lane >> 3) & 1));
                uint32_t vh2[2], vl2[2];
                ldmatrix_x2(vh2, va);
                ldmatrix_x2(vl2, va + AT_B);
                mma_bf16(O[hf], ph4, vh2);
                mma_bf16(O[hf], pl4, vh2);
                mma_bf16(O[hf], ph4, vl2);
            }
        }
        cur ^= 1;
    }

    // --- Epilogue: ctx hi/lo to [b*SEQ+s][DMODEL] ---
    const float inv0 = 1.0f / l0;
    const float inv1 = 1.0f / l1;
    const int b    = bh >> 4;
    const int head = bh & 15;
    const int r0   = qBase + w * 16 + (lane >> 2);
    #pragma unroll
    for (int j = 0; j < 8; j++) {
        const int col = head * HDIM + 8 * j + 2 * (lane & 3);
        const size_t i0 = (size_t)(b * SEQ + r0) * DMODEL + col;
        const size_t i1 = (size_t)(b * SEQ + r0 + 8) * DMODEL + col;
        __nv_bfloat162 hv, lv;
        split2(O[j][0] * inv0, hv.x, lv.x);
        split2(O[j][1] * inv0, hv.y, lv.y);
        *reinterpret_cast<__nv_bfloat162*>(g_ch + i0) = hv;
        *reinterpret_cast<__nv_bfloat162*>(g_cl + i0) = lv;
        split2(O[j][2] * inv1, hv.x, lv.x);
        split2(O[j][3] * inv1, hv.y, lv.y);
        *reinterpret_cast<__nv_bfloat162*>(g_ch + i1) = hv;
        *reinterpret_cast<__nv_bfloat162*>(g_cl + i1) = lv;
    }
}

// ---------------------------------------------------------------------------
// Launch
// ---------------------------------------------------------------------------
extern "C" void kernel_launch(void* const* d_in, const int* in_sizes, int n_in,
                              void* d_out, int out_size)
{
    const float* x  = (const float*)d_in[0];
    const float* wq = (const float*)d_in[1];
    const float* bq = (const float*)d_in[2];
    const float* wk = (const float*)d_in[3];
    const float* bk = (const float*)d_in[4];
    const float* wv = (const float*)d_in[5];
    const float* bv = (const float*)d_in[6];
    const float* wo = (const float*)d_in[7];
    const float* bo = (const float*)d_in[8];
    float* out = (float*)d_out;

    __nv_bfloat16 *xh, *xl, *wh, *wl, *qh, *ql, *kh, *kl, *vh, *vl, *ch, *cl;
    cudaGetSymbolAddress((void**)&xh, g_xh);
    cudaGetSymbolAddress((void**)&xl, g_xl);
    cudaGetSymbolAddress((void**)&wh, g_wh);
    cudaGetSymbolAddress((void**)&wl, g_wl);
    cudaGetSymbolAddress((void**)&qh, g_qh);
    cudaGetSymbolAddress((void**)&ql, g_ql);
    cudaGetSymbolAddress((void**)&kh, g_kh);
    cudaGetSymbolAddress((void**)&kl, g_kl);
    cudaGetSymbolAddress((void**)&vh, g_vh);
    cudaGetSymbolAddress((void**)&vl, g_vl);
    cudaGetSymbolAddress((void**)&ch, g_ch);
    cudaGetSymbolAddress((void**)&cl, g_cl);

    const int NX = MROWS * DMODEL;
    const int NW = DMODEL * DMODEL;
    const float* wsrc[4] = {wq, wk, wv, wo};

    split_bf16_kernel<<<NX / 4 / 256, 256>>>(x, xh, xl, NX);
    for (int i = 0; i < 4; i++)
        split_bf16_kernel<<<NW / 4 / 256, 256>>>(wsrc[i], wh + (size_t)i * NW,
                                                 wl + (size_t)i * NW, NW);

    cudaFuncSetAttribute(mma_gemm<0>, cudaFuncAttributeMaxDynamicSharedMemorySize, GEMM_SMEM);
    cudaFuncSetAttribute(mma_gemm<1>, cudaFuncAttributeMaxDynamicSharedMemorySize, GEMM_SMEM);
    cudaFuncSetAttribute(mma_gemm<2>, cudaFuncAttributeMaxDynamicSharedMemorySize, GEMM_SMEM);
    cudaFuncSetAttribute(attn_mma_kernel, cudaFuncAttributeMaxDynamicSharedMemorySize, ATTN_SMEM);

    dim3 gemmGrid(DMODEL / 128, MROWS / 128);
    dim3 blk(256);

    // Q/K projections -> split bf16 [bh][s][hd]; Q scaled by 0.125
    mma_gemm<1><<<gemmGrid, blk, GEMM_SMEM>>>(xh, xl, wh + 0 * (size_t)NW, wl + 0 * (size_t)NW,
                                              bq, nullptr, qh, ql, 0.125f);
    mma_gemm<1><<<gemmGrid, blk, GEMM_SMEM>>>(xh, xl, wh + 1 * (size_t)NW, wl + 1 * (size_t)NW,
                                              bk, nullptr, kh, kl, 1.0f);
    // V projection -> split bf16 TRANSPOSED [bh][hd][s]
    mma_gemm<2><<<gemmGrid, blk, GEMM_SMEM>>>(xh, xl, wh + 2 * (size_t)NW, wl + 2 * (size_t)NW,
                                              bv, nullptr, vh, vl, 1.0f);

    // Tensor-core flash attention (double-buffered)
    dim3 attnGrid(SEQ / 64, BATCH * NHEAD);
    attn_mma_kernel<<<attnGrid, 128, ATTN_SMEM>>>();

    // Output projection (fp32 out)
    mma_gemm<0><<<gemmGrid, blk, GEMM_SMEM>>>(ch, cl, wh + 3 * (size_t)NW, wl + 3 * (size_t)NW,
                                              bo, out, nullptr, nullptr, 1.0f);
}